// round 6
// baseline (speedup 1.0000x reference)
#include <cuda_runtime.h>

#define TT 512
#define BB 64
#define II 512
#define HH 512

#define WS2 18   // float2 stride per k2 row for weights (16 used, padded, 16B-aligned rows)
#define HS2 18   // float2 stride per k2 row for h (16 used, padded)

// Static device scratch (no allocations allowed)
__device__ float g_xp[2][TT][BB][HH];    // input projections per direction
__device__ float g_h[2][2][BB][HH];      // [dir][buf][b][h] double-buffered state
__device__ unsigned g_flag[2][128][32];  // per-CTA barrier flags, 128B padded (monotonic)

typedef unsigned long long ull;

__device__ __forceinline__ void fma2(ull& acc, ull a, ull b) {
    asm("fma.rn.f32x2 %0, %1, %2, %0;" : "+l"(acc) : "l"(a), "l"(b));
}
__device__ __forceinline__ ull add2(ull a, ull b) {
    ull r; asm("add.rn.f32x2 %0, %1, %2;" : "=l"(r) : "l"(a), "l"(b)); return r;
}
__device__ __forceinline__ float2 unpack2(ull v) {
    float2 r; asm("mov.b64 {%0, %1}, %2;" : "=f"(r.x), "=f"(r.y) : "l"(v)); return r;
}
__device__ __forceinline__ unsigned ld_acq(const unsigned* p) {
    unsigned v; asm volatile("ld.acquire.gpu.u32 %0, [%1];" : "=r"(v) : "l"(p) : "memory");
    return v;
}
__device__ __forceinline__ void st_rel(unsigned* p, unsigned v) {
    asm volatile("st.release.gpu.u32 [%0], %1;" :: "l"(p), "r"(v) : "memory");
}

// ---------------------------------------------------------------------------
// Phase 1: xp[dir][t][b][n] = sum_i x[b][t][i] * W[n][i] + bias[n]
// Grid (8, 512, 2); 256 threads; 64x64 tile; 4x4 thread tile; k-parity packed.
// ---------------------------------------------------------------------------
__global__ __launch_bounds__(256) void xproj_kernel(
    const float* __restrict__ x,
    const float* __restrict__ Wf, const float* __restrict__ bf,
    const float* __restrict__ Wb, const float* __restrict__ bbias) {
    const int dir = blockIdx.z;
    const float* __restrict__ W    = dir ? Wb : Wf;
    const float* __restrict__ bias = dir ? bbias : bf;
    const int t = blockIdx.y;
    const int n_base = blockIdx.x * 64;

    __shared__ float2 a2[8][66];   // [k2][m]  {x[m][2k2], x[m][2k2+1]}
    __shared__ float2 b2[8][66];   // [k2][n]

    const int tid = threadIdx.x;
    const int w = tid >> 5, lane = tid & 31;
    const int mgrp = ((w >> 1) << 2) | (lane >> 3);  // 0..15
    const int ngrp = ((w & 1) << 3) | (lane & 7);    // 0..15
    const int m0 = mgrp << 2, n0l = ngrp << 2;

    const int lr = tid >> 2;          // loader row 0..63
    const int lq = (tid & 3) << 2;    // k offset 0,4,8,12
    const float* arow = x + ((size_t)lr * TT + t) * II + lq;
    const float* brow = W + (size_t)(n_base + lr) * II + lq;

    ull acc[4][4];
#pragma unroll
    for (int i = 0; i < 4; i++)
#pragma unroll
        for (int j = 0; j < 4; j++) acc[i][j] = 0ull;

    for (int st = 0; st < 32; st++) {
        float4 pa = *(const float4*)(arow + st * 16);
        float4 pb = *(const float4*)(brow + st * 16);
        __syncthreads();
        a2[(lq >> 1) + 0][lr] = make_float2(pa.x, pa.y);
        a2[(lq >> 1) + 1][lr] = make_float2(pa.z, pa.w);
        b2[(lq >> 1) + 0][lr] = make_float2(pb.x, pb.y);
        b2[(lq >> 1) + 1][lr] = make_float2(pb.z, pb.w);
        __syncthreads();
#pragma unroll
        for (int k2 = 0; k2 < 8; k2++) {
            ulonglong2 av0 = *(const ulonglong2*)&a2[k2][m0];
            ulonglong2 av1 = *(const ulonglong2*)&a2[k2][m0 + 2];
            ulonglong2 bv0 = *(const ulonglong2*)&b2[k2][n0l];
            ulonglong2 bv1 = *(const ulonglong2*)&b2[k2][n0l + 2];
            ull am[4] = {av0.x, av0.y, av1.x, av1.y};
            ull bn[4] = {bv0.x, bv0.y, bv1.x, bv1.y};
#pragma unroll
            for (int i = 0; i < 4; i++)
#pragma unroll
                for (int j = 0; j < 4; j++)
                    fma2(acc[i][j], am[i], bn[j]);
        }
    }

    float4 bv = *(const float4*)(bias + n_base + n0l);
#pragma unroll
    for (int i = 0; i < 4; i++) {
        float2 s0 = unpack2(acc[i][0]);
        float2 s1 = unpack2(acc[i][1]);
        float2 s2 = unpack2(acc[i][2]);
        float2 s3 = unpack2(acc[i][3]);
        float4 v;
        v.x = s0.x + s0.y + bv.x;
        v.y = s1.x + s1.y + bv.y;
        v.z = s2.x + s2.y + bv.z;
        v.w = s3.x + s3.y + bv.w;
        *(float4*)&g_xp[dir][t][m0 + i][n_base + n0l] = v;
    }
}

// ---------------------------------------------------------------------------
// Phase 2: persistent recurrence. 256 CTAs (128/dir), 128 threads, 2 CTAs/SM.
// CTA tile 16b x 16n; thread tile 2b x 2n; k-split by 2 (64 threads each).
// Wh slice SMEM-resident; h staged transposed [k2][b].
// Per-direction distributed-flag barrier (replay-monotonic).
// ---------------------------------------------------------------------------
__global__ __launch_bounds__(128, 2) void rnn_persist(
    const float* __restrict__ Whf, const float* __restrict__ Whb,
    const float* __restrict__ h0f, const float* __restrict__ h0b,
    float* __restrict__ out) {
    extern __shared__ char smem[];
    float2* ws = (float2*)smem;                       // [256][WS2]
    float2* hs = (float2*)(smem + 256 * WS2 * 8);     // [256][HS2]
    ulonglong2* red = (ulonglong2*)hs;                // reuse for k-half reduction

    const int cta = blockIdx.x;
    const int dir = cta & 1;
    const int slice = cta >> 1;             // 0..127
    const int b_base = (slice >> 5) * 16;   // 4 b-groups
    const int n_base = (slice & 31) * 16;   // 32 n-slices
    const float* __restrict__ Wh = dir ? Whb : Whf;
    const float* __restrict__ h0 = dir ? h0b : h0f;
    const int tid = threadIdx.x;
    const int khalf = tid >> 6;             // 0: k2 0..127, 1: k2 128..255
    const int ctid = tid & 63;
    const int bgrp = ctid >> 3;             // 0..7
    const int ngrp = ctid & 7;              // 0..7
    const int b0 = b_base + 2 * bgrp;
    const int n0 = n_base + 2 * ngrp;

    // one-time weight fill: ws[k2][nl] = {W[n][2k2], W[n][2k2+1]}
    for (int idx = tid; idx < 16 * 256; idx += 128) {
        int nl = idx >> 8, k2 = idx & 255;
        ws[k2 * WS2 + nl] =
            *(const float2*)(Wh + (size_t)(n_base + nl) * HH + 2 * k2);
    }

    const int sb = tid >> 3;     // staging row 0..15
    const int sc = tid & 7;      // staging col base
    const float2* wsp = ws + (size_t)khalf * 128 * WS2 + 2 * ngrp;
    const float2* hsp = hs + (size_t)khalf * 128 * HS2 + 2 * bgrp;

    // replay-monotonic barrier base: read OWN flag (only this CTA writes it)
    const unsigned base = ld_acq(&g_flag[dir][slice][0]);
    const unsigned* pollf = &g_flag[dir][tid][0];   // 128 threads poll 128 flags
    __syncthreads();   // ws fill complete

    for (int s = 0; s < TT; s++) {
        const int t = dir ? (TT - 1 - s) : s;
        const float* __restrict__ hin =
            (s == 0) ? h0 : (const float*)g_h[dir][s & 1];
        float* __restrict__ hout = (float*)g_h[dir][(s & 1) ^ 1];

        // stage h slice (16 x 512) transposed into hs
#pragma unroll
        for (int i = 0; i < 16; i++) {
            int c = sc + 8 * i;   // float4 chunk 0..127
            float4 v = *(const float4*)(hin + (size_t)(b_base + sb) * HH + 4 * c);
            hs[(2 * c) * HS2 + sb]     = make_float2(v.x, v.y);
            hs[(2 * c + 1) * HS2 + sb] = make_float2(v.z, v.w);
        }
        float2 xp0, xp1;
        if (khalf == 0) {
            xp0 = *(const float2*)&g_xp[dir][t][b0][n0];
            xp1 = *(const float2*)&g_xp[dir][t][b0 + 1][n0];
        }
        __syncthreads();

        ull a00 = 0ull, a01 = 0ull, a10 = 0ull, a11 = 0ull;
#pragma unroll 8
        for (int k2 = 0; k2 < 128; k2++) {
            ulonglong2 wv = *(const ulonglong2*)(wsp + k2 * WS2);
            ulonglong2 hv = *(const ulonglong2*)(hsp + k2 * HS2);
            fma2(a00, hv.x, wv.x); fma2(a01, hv.x, wv.y);
            fma2(a10, hv.y, wv.x); fma2(a11, hv.y, wv.y);
        }

        __syncthreads();   // hs reads done; reuse as reduction scratch
        if (khalf == 1) {
            red[ctid * 2 + 0] = make_ulonglong2(a00, a01);
            red[ctid * 2 + 1] = make_ulonglong2(a10, a11);
        }
        __syncthreads();

        if (khalf == 0) {
            ulonglong2 p0 = red[ctid * 2 + 0];
            ulonglong2 p1 = red[ctid * 2 + 1];
            float2 s00 = unpack2(add2(a00, p0.x));
            float2 s01 = unpack2(add2(a01, p0.y));
            float2 s10 = unpack2(add2(a10, p1.x));
            float2 s11 = unpack2(add2(a11, p1.y));
            float v00 = tanhf(s00.x + s00.y + xp0.x);
            float v01 = tanhf(s01.x + s01.y + xp0.y);
            float v10 = tanhf(s10.x + s10.y + xp1.x);
            float v11 = tanhf(s11.x + s11.y + xp1.y);

            *(float2*)(hout + (size_t)b0 * HH + n0)       = make_float2(v00, v01);
            *(float2*)(hout + (size_t)(b0 + 1) * HH + n0) = make_float2(v10, v11);
            *(float2*)(out + ((size_t)b0 * TT + t) * (2 * HH) +
                       (size_t)dir * HH + n0) = make_float2(v00, v01);
            *(float2*)(out + ((size_t)(b0 + 1) * TT + t) * (2 * HH) +
                       (size_t)dir * HH + n0) = make_float2(v10, v11);
            if (s == TT - 1) {
                float* hT = out + (size_t)BB * TT * 2 * HH + (size_t)dir * BB * HH;
                *(float2*)(hT + (size_t)b0 * HH + n0)       = make_float2(v00, v01);
                *(float2*)(hT + (size_t)(b0 + 1) * HH + n0) = make_float2(v10, v11);
            }
        }
        if (s == TT - 1) break;

        // distributed-flag grid barrier (per direction)
        __syncthreads();                 // all hout writes issued
        if (tid == 0) st_rel(&g_flag[dir][slice][0], base + s + 1);
        {
            const unsigned tgt = base + (unsigned)(s + 1);
            while (ld_acq(pollf) < tgt) {}
        }
        __syncthreads();
    }
}

extern "C" void kernel_launch(void* const* d_in, const int* in_sizes, int n_in,
                              void* d_out, int out_size) {
    const float* x     = (const float*)d_in[0];
    const float* h0f   = (const float*)d_in[1];
    const float* h0b   = (const float*)d_in[2];
    const float* Wxf_w = (const float*)d_in[3];
    const float* Wxf_b = (const float*)d_in[4];
    const float* Whf_w = (const float*)d_in[5];
    const float* Wxb_w = (const float*)d_in[6];
    const float* Wxb_b = (const float*)d_in[7];
    const float* Whb_w = (const float*)d_in[8];
    float* out = (float*)d_out;

    static int smem_set = 0;
    const int smem_bytes = 256 * WS2 * 8 + 256 * HS2 * 8;   // 73728
    if (!smem_set) {
        cudaFuncSetAttribute(rnn_persist,
                             cudaFuncAttributeMaxDynamicSharedMemorySize,
                             smem_bytes);
        smem_set = 1;
    }

    xproj_kernel<<<dim3(HH / 64, TT, 2), 256>>>(x, Wxf_w, Wxf_b, Wxb_w, Wxb_b);
    rnn_persist<<<256, 128, smem_bytes>>>(Whf_w, Whb_w, h0f, h0b, out);
}

// round 7
// speedup vs baseline: 1.2114x; 1.2114x over previous
#include <cuda_runtime.h>

#define TT 512
#define BB 64
#define II 512
#define HH 512

// smem layout constants (element strides)
#define WSS 34     // float2 stride per k2 row of weights (32 used)
#define HSS 259    // float2 stride per batch row of h (256 used, odd-ish for banks)
#define RPS 146    // ull stride per outpos in reduction array
#define WS_BYTES (256 * WSS * 8)            // 69632
#define HS_BYTES (16 * HSS * 8)             // 33152
#define RED_OFF  (WS_BYTES + HS_BYTES)      // 102784 (16B aligned)
#define SMEM_TOTAL (RED_OFF + 4672 * 8)     // 140160

// Static device scratch (no allocations allowed)
__device__ float g_xp[2][TT][BB][HH];    // input projections per direction
__device__ float g_h[2][2][BB][HH];      // [dir][buf][b][h] double-buffered state
__device__ unsigned g_flag[2][64][32];   // per-CTA barrier flags, 128B padded (monotonic)

typedef unsigned long long ull;

__device__ __forceinline__ void fma2(ull& acc, ull a, ull b) {
    asm("fma.rn.f32x2 %0, %1, %2, %0;" : "+l"(acc) : "l"(a), "l"(b));
}
__device__ __forceinline__ ull add2(ull a, ull b) {
    ull r; asm("add.rn.f32x2 %0, %1, %2;" : "=l"(r) : "l"(a), "l"(b)); return r;
}
__device__ __forceinline__ float2 unpack2(ull v) {
    float2 r; asm("mov.b64 {%0, %1}, %2;" : "=f"(r.x), "=f"(r.y) : "l"(v)); return r;
}
__device__ __forceinline__ unsigned ld_acq(const unsigned* p) {
    unsigned v; asm volatile("ld.acquire.gpu.u32 %0, [%1];" : "=r"(v) : "l"(p) : "memory");
    return v;
}
__device__ __forceinline__ void st_rel(unsigned* p, unsigned v) {
    asm volatile("st.release.gpu.u32 [%0], %1;" :: "l"(p), "r"(v) : "memory");
}

// ---------------------------------------------------------------------------
// Phase 1: xp[dir][t][b][n] = sum_i x[b][t][i] * W[n][i] + bias[n]
// ---------------------------------------------------------------------------
__global__ __launch_bounds__(256) void xproj_kernel(
    const float* __restrict__ x,
    const float* __restrict__ Wf, const float* __restrict__ bf,
    const float* __restrict__ Wb, const float* __restrict__ bbias) {
    const int dir = blockIdx.z;
    const float* __restrict__ W    = dir ? Wb : Wf;
    const float* __restrict__ bias = dir ? bbias : bf;
    const int t = blockIdx.y;
    const int n_base = blockIdx.x * 64;

    __shared__ float2 a2[8][66];   // [k2][m]
    __shared__ float2 b2[8][66];   // [k2][n]

    const int tid = threadIdx.x;
    const int w = tid >> 5, lane = tid & 31;
    const int mgrp = ((w >> 1) << 2) | (lane >> 3);  // 0..15
    const int ngrp = ((w & 1) << 3) | (lane & 7);    // 0..15
    const int m0 = mgrp << 2, n0l = ngrp << 2;

    const int lr = tid >> 2;
    const int lq = (tid & 3) << 2;
    const float* arow = x + ((size_t)lr * TT + t) * II + lq;
    const float* brow = W + (size_t)(n_base + lr) * II + lq;

    ull acc[4][4];
#pragma unroll
    for (int i = 0; i < 4; i++)
#pragma unroll
        for (int j = 0; j < 4; j++) acc[i][j] = 0ull;

    for (int st = 0; st < 32; st++) {
        float4 pa = *(const float4*)(arow + st * 16);
        float4 pb = *(const float4*)(brow + st * 16);
        __syncthreads();
        a2[(lq >> 1) + 0][lr] = make_float2(pa.x, pa.y);
        a2[(lq >> 1) + 1][lr] = make_float2(pa.z, pa.w);
        b2[(lq >> 1) + 0][lr] = make_float2(pb.x, pb.y);
        b2[(lq >> 1) + 1][lr] = make_float2(pb.z, pb.w);
        __syncthreads();
#pragma unroll
        for (int k2 = 0; k2 < 8; k2++) {
            ulonglong2 av0 = *(const ulonglong2*)&a2[k2][m0];
            ulonglong2 av1 = *(const ulonglong2*)&a2[k2][m0 + 2];
            ulonglong2 bv0 = *(const ulonglong2*)&b2[k2][n0l];
            ulonglong2 bv1 = *(const ulonglong2*)&b2[k2][n0l + 2];
            ull am[4] = {av0.x, av0.y, av1.x, av1.y};
            ull bn[4] = {bv0.x, bv0.y, bv1.x, bv1.y};
#pragma unroll
            for (int i = 0; i < 4; i++)
#pragma unroll
                for (int j = 0; j < 4; j++)
                    fma2(acc[i][j], am[i], bn[j]);
        }
    }

    float4 bv = *(const float4*)(bias + n_base + n0l);
#pragma unroll
    for (int i = 0; i < 4; i++) {
        float2 s0 = unpack2(acc[i][0]);
        float2 s1 = unpack2(acc[i][1]);
        float2 s2 = unpack2(acc[i][2]);
        float2 s3 = unpack2(acc[i][3]);
        float4 v;
        v.x = s0.x + s0.y + bv.x;
        v.y = s1.x + s1.y + bv.y;
        v.z = s2.x + s2.y + bv.z;
        v.w = s3.x + s3.y + bv.w;
        *(float4*)&g_xp[dir][t][m0 + i][n_base + n0l] = v;
    }
}

// ---------------------------------------------------------------------------
// Phase 2: persistent recurrence. 128 CTAs (64/dir), 256 threads, 1 CTA/SM.
// CTA tile 16b x 32n; thread tile 4b x 4n; k-split 8 (one k-slice per warp).
// Weights SMEM-resident; h staged [b][k2]; 8-way smem reduction; flag barrier.
// ---------------------------------------------------------------------------
__global__ __launch_bounds__(256, 1) void rnn_persist(
    const float* __restrict__ Whf, const float* __restrict__ Whb,
    const float* __restrict__ h0f, const float* __restrict__ h0b,
    float* __restrict__ out) {
    extern __shared__ char smem[];
    float2* ws = (float2*)smem;                 // [256][WSS]
    float2* hs = (float2*)(smem + WS_BYTES);    // [16][HSS]
    ull* red   = (ull*)(smem + RED_OFF);        // [32][RPS]-ish flat

    const int cta = blockIdx.x;
    const int dir = cta & 1;
    const int slice = cta >> 1;             // 0..63
    const int b_base = (slice >> 4) * 16;   // 4 b-groups
    const int n_base = (slice & 15) * 32;   // 16 n-groups
    const float* __restrict__ Wh = dir ? Whb : Whf;
    const float* __restrict__ h0 = dir ? h0b : h0f;
    const int tid = threadIdx.x;
    const int ks = tid >> 5;                // warp id = k-slice (k2 in [32ks,32ks+32))
    const int lane = tid & 31;
    const int ngrp = lane >> 2;             // 0..7  (4 n each)
    const int bgrp = lane & 3;              // 0..3  (4 b each)

    // one-time weight fill: ws[k2][nl] = {W[n][2k2], W[n][2k2+1]}
    for (int idx = tid; idx < 32 * 256; idx += 256) {
        int nl = idx >> 8, k2 = idx & 255;
        ws[k2 * WSS + nl] =
            *(const float2*)(Wh + (size_t)(n_base + nl) * HH + 2 * k2);
    }

    // reducer assignment: 2 outputs (adjacent n) per thread
    const int ro = tid >> 3, j = tid & 7;   // outpos, pair index
    const int i0 = 2 * j;
    const int rb = b_base + (ro & 3) * 4 + (i0 >> 2);
    const int rn = n_base + (ro >> 2) * 4 + (i0 & 3);

    const int sbr = tid >> 4;    // staging batch row 0..15
    const int sc = tid & 15;     // staging chunk base

    const float2* wp = ws + (size_t)(ks * 32) * WSS + 4 * ngrp;
    const float2* hp = hs + (size_t)(4 * bgrp) * HSS + ks * 32;

    // replay-monotonic barrier base (only this CTA writes its flag)
    const unsigned base = ld_acq(&g_flag[dir][slice][0]);
    __syncthreads();

    for (int s = 0; s < TT; s++) {
        const int t = dir ? (TT - 1 - s) : s;
        const float* __restrict__ hin =
            (s == 0) ? h0 : (const float*)g_h[dir][s & 1];
        float* __restrict__ hout = (float*)g_h[dir][(s & 1) ^ 1];

        // stage h slice (16 x 512) into hs[b][k2] (float2 per k2)
#pragma unroll
        for (int i = 0; i < 8; i++) {
            int c = sc + 16 * i;   // float4 chunk 0..127
            float4 v = *(const float4*)(hin + (size_t)(b_base + sbr) * HH + 4 * c);
            hs[sbr * HSS + 2 * c]     = make_float2(v.x, v.y);
            hs[sbr * HSS + 2 * c + 1] = make_float2(v.z, v.w);
        }
        float2 xpv = *(const float2*)&g_xp[dir][t][rb][rn];
        __syncthreads();

        // mainloop: 4b x 4n per thread over this warp's 32 k2
        ull acc[16];
#pragma unroll
        for (int i = 0; i < 16; i++) acc[i] = 0ull;
#pragma unroll 8
        for (int kk = 0; kk < 32; kk++) {
            ull hv0 = *(const ull*)(hp + kk);
            ull hv1 = *(const ull*)(hp + kk + HSS);
            ull hv2 = *(const ull*)(hp + kk + 2 * HSS);
            ull hv3 = *(const ull*)(hp + kk + 3 * HSS);
            ulonglong2 w01 = *(const ulonglong2*)(wp + (size_t)kk * WSS);
            ulonglong2 w23 = *(const ulonglong2*)(wp + (size_t)kk * WSS + 2);
            fma2(acc[0],  hv0, w01.x); fma2(acc[1],  hv0, w01.y);
            fma2(acc[2],  hv0, w23.x); fma2(acc[3],  hv0, w23.y);
            fma2(acc[4],  hv1, w01.x); fma2(acc[5],  hv1, w01.y);
            fma2(acc[6],  hv1, w23.x); fma2(acc[7],  hv1, w23.y);
            fma2(acc[8],  hv2, w01.x); fma2(acc[9],  hv2, w01.y);
            fma2(acc[10], hv2, w23.x); fma2(acc[11], hv2, w23.y);
            fma2(acc[12], hv3, w01.x); fma2(acc[13], hv3, w01.y);
            fma2(acc[14], hv3, w23.x); fma2(acc[15], hv3, w23.y);
        }

        // write partials: red[outpos(=lane)][i][ks]
#pragma unroll
        for (int i = 0; i < 16; i++)
            red[lane * RPS + i * 9 + ks] = acc[i];
        __syncthreads();

        // 8-way reduction: this thread's 2 outputs are i0 and i0+1 at outpos ro
        {
            const ulonglong2* q = (const ulonglong2*)(red + ro * RPS + 18 * j);
            ulonglong2 q0 = q[0], q1 = q[1], q2 = q[2], q3 = q[3];
            ulonglong2 q4 = q[4], q5 = q[5], q6 = q[6], q7 = q[7], q8 = q[8];
            ull s0 = add2(add2(add2(q0.x, q0.y), add2(q1.x, q1.y)),
                          add2(add2(q2.x, q2.y), add2(q3.x, q3.y)));
            ull s1 = add2(add2(add2(q4.y, q5.x), add2(q5.y, q6.x)),
                          add2(add2(q6.y, q7.x), add2(q7.y, q8.x)));
            float2 f0 = unpack2(s0);
            float2 f1 = unpack2(s1);
            float v0 = tanhf(f0.x + f0.y + xpv.x);
            float v1 = tanhf(f1.x + f1.y + xpv.y);
            *(float2*)(hout + (size_t)rb * HH + rn) = make_float2(v0, v1);
            *(float2*)(out + ((size_t)rb * TT + t) * (2 * HH) +
                       (size_t)dir * HH + rn) = make_float2(v0, v1);
            if (s == TT - 1) {
                float* hT = out + (size_t)BB * TT * 2 * HH + (size_t)dir * BB * HH;
                *(float2*)(hT + (size_t)rb * HH + rn) = make_float2(v0, v1);
            }
        }
        if (s == TT - 1) break;

        // distributed-flag grid barrier (per direction)
        __syncthreads();                 // all hout writes issued
        if (tid == 0) st_rel(&g_flag[dir][slice][0], base + s + 1);
        if (tid < 64) {
            const unsigned tgt = base + (unsigned)(s + 1);
            const unsigned* f = &g_flag[dir][tid][0];
            while (ld_acq(f) < tgt) {}
        }
        __syncthreads();
    }
}

extern "C" void kernel_launch(void* const* d_in, const int* in_sizes, int n_in,
                              void* d_out, int out_size) {
    const float* x     = (const float*)d_in[0];
    const float* h0f   = (const float*)d_in[1];
    const float* h0b   = (const float*)d_in[2];
    const float* Wxf_w = (const float*)d_in[3];
    const float* Wxf_b = (const float*)d_in[4];
    const float* Whf_w = (const float*)d_in[5];
    const float* Wxb_w = (const float*)d_in[6];
    const float* Wxb_b = (const float*)d_in[7];
    const float* Whb_w = (const float*)d_in[8];
    float* out = (float*)d_out;

    static int smem_set = 0;
    if (!smem_set) {
        cudaFuncSetAttribute(rnn_persist,
                             cudaFuncAttributeMaxDynamicSharedMemorySize,
                             SMEM_TOTAL);
        smem_set = 1;
    }

    xproj_kernel<<<dim3(HH / 64, TT, 2), 256>>>(x, Wxf_w, Wxf_b, Wxb_w, Wxb_b);
    rnn_persist<<<128, 256, SMEM_TOTAL>>>(Whf_w, Whb_w, h0f, h0b, out);
}